// round 9
// baseline (speedup 1.0000x reference)
#include <cuda_runtime.h>
#include <cuda_fp16.h>
#include <cstdint>

#define NN      8192
#define EE      65536
#define IND     128
#define HID     64
#define NEXT    4352        // 4096 (A'') + 64 (p2) + 64 (Ls) + 64 (Ld) + 64 (pad)
#define XW      256         // extras row width: p2[0:64] Ls[64:128] Ld[128:192] pad[192:256]
#define BN_EPS  1e-5f

// ---------------- scratch (device globals; allocation-free) ----------------
__device__ float g_W[NEXT * IND];          // extended weight  [4352,128] fp32
__device__ float g_bias[NEXT];             // extended bias
__device__ float g_A[(size_t)NN * 4096];   // per-node A'' [8192,4096] ~134MB
__device__ float g_X[(size_t)NN * XW];     // per-node extras [8192,256] 8MB
__device__ float g_c[HID];                 // per-channel constant (bias+BN folded)
__device__ __half g_hh[NN * IND];          // h hi (fp16)
__device__ __half g_hl[NN * IND];          // h lo (fp16)
__device__ __half g_wh[NEXT * IND];        // W hi (fp16)
__device__ int   g_cnt[NN];
__device__ int   g_cur[NN];
__device__ int   g_off[NN + 1];
__device__ int   g_perm[EE];

// ---------------- prep 1: extra weight rows, biases, constants -------------
__global__ void prep1_kernel(const float* __restrict__ ep2w,
                             const float* __restrict__ ep2b,
                             const float* __restrict__ ep3w,
                             const float* __restrict__ ep3b,
                             const float* __restrict__ proj1b,
                             const float* __restrict__ proj2w,
                             const float* __restrict__ proj2b,
                             const float* __restrict__ convw,
                             const float* __restrict__ convb,
                             const float* __restrict__ gamma,
                             const float* __restrict__ beta,
                             const float* __restrict__ mean,
                             const float* __restrict__ var) {
    __shared__ float red[128];
    int i = blockIdx.x;
    int w = threadIdx.x;
    float s = gamma[i] * rsqrtf(var[i] + BN_EPS);

    float e0 = ep2w[i * IND + w];
    float ep = (w + 1 < IND) ? ep2w[i * IND + w + 1] : 0.f;
    float em = (w >= 1)      ? ep2w[i * IND + w - 1] : 0.f;
    g_W[(4160 + i) * IND + w] = s * (convw[0] * ep + convw[1] * e0 + convw[2] * em); // Ls
    g_W[(4224 + i) * IND + w] = s * (convw[3] * ep + convw[4] * e0 + convw[5] * em); // Ld
    g_W[(4096 + i) * IND + w] = proj2w[i * IND + w];                                 // p2
    g_W[(4288 + i) * IND + w] = 0.f;                                                 // pad

    red[w] = e0;
    __syncthreads();
    for (int o = 64; o > 0; o >>= 1) {
        if (w < o) red[w] += red[w + o];
        __syncthreads();
    }
    if (w == 0) {
        float tot = red[0];
        g_c[i] = s * (ep3b[i] + convb[0] * tot + ep2b[i]) + beta[i] - mean[i] * s;
        g_bias[4096 + i] = proj2b[i];
        g_bias[4160 + i] = 0.f;
        g_bias[4224 + i] = 0.f;
        g_bias[4288 + i] = 0.f;
    }
    if (w < 64) {
        int d = w;
        float acc = 0.f;
        #pragma unroll 8
        for (int j = 0; j < 64; j++) acc += ep3w[i * 64 + j] * proj1b[j * 64 + d];
        g_bias[i * 64 + d] = s * acc;
    }
}

// ---------------- prep 2: main W'' rows = s_i * ep3 @ proj1_flat -----------
__global__ void prep2_kernel(const float* __restrict__ proj1w,
                             const float* __restrict__ ep3w,
                             const float* __restrict__ gamma,
                             const float* __restrict__ var) {
    __shared__ float ep3s[4096];
    __shared__ float ptile[4096];
    __shared__ float ss[64];
    int tid = threadIdx.x;
    int mb = blockIdx.x * 64;
    for (int idx = tid; idx < 4096; idx += 256) ep3s[idx] = ep3w[idx];
    if (tid < 64) ss[tid] = gamma[tid] * rsqrtf(var[tid] + BN_EPS);
    for (int idx = tid; idx < 4096; idx += 256) {
        int j = idx >> 6, mm = idx & 63;
        ptile[idx] = proj1w[j * 8192 + mb + mm];
    }
    __syncthreads();
    for (int o = tid; o < 4096; o += 256) {
        int i = o >> 6, mm = o & 63;
        float acc = 0.f;
        #pragma unroll 8
        for (int j = 0; j < 64; j++) acc += ep3s[i * 64 + j] * ptile[j * 64 + mm];
        int m = mb + mm;
        int d = m >> 7, w = m & 127;
        g_W[(i * 64 + d) * IND + w] = ss[i] * acc;
    }
}

// ---------------- fused fp16 hi/lo converter (h and W) ---------------------
// grid covers h (1,048,576 el) then W (557,056 el), 4 el/thread
__global__ void conv_hw_kernel(const float* __restrict__ h) {
    int idx = (blockIdx.x * 256 + threadIdx.x) * 4;
    if (idx < NN * IND) {
        float4 v = *(const float4*)&h[idx];
        float xs[4] = {v.x, v.y, v.z, v.w};
        #pragma unroll
        for (int q = 0; q < 4; q++) {
            __half hi = __float2half_rn(xs[q]);
            g_hh[idx + q] = hi;
            g_hl[idx + q] = __float2half_rn(xs[q] - __half2float(hi));
        }
    } else {
        int j = idx - NN * IND;
        float4 v = *(const float4*)&g_W[j];
        float xs[4] = {v.x, v.y, v.z, v.w};
        #pragma unroll
        for (int q = 0; q < 4; q++)
            g_wh[j + q] = __float2half_rn(xs[q]);
    }
}

// ---------------- HMMA GEMM: [g_A|g_X] = h @ W^T + bias --------------------
// mma.sync.m16n8k16 fp16, 2-pass hi/lo split (hi_h*hi_w + lo_h*hi_w), fp32 acc.
// CTA = 128x128 tile, K=128 resident, 3 smem tiles -> 2 CTAs/SM.
// 8 warps = 4(m) x 2(n); per warp 32x64 = 2 m16-tiles x 8 n8-tiles.
#define TS       136                 // smem row stride in fp16 (272B; conflict-free frags)
#define SA_HI    0
#define SA_LO    (128 * TS)
#define SB_HI    (2 * 128 * TS)
#define SM_FP16  (3 * 128 * TS)      // 52224 halfs = 104448 bytes

__device__ __forceinline__ void mma16816(float* c, const uint32_t* a, const uint32_t* b) {
    asm volatile(
        "mma.sync.aligned.m16n8k16.row.col.f32.f16.f16.f32 "
        "{%0,%1,%2,%3}, {%4,%5,%6,%7}, {%8,%9}, {%0,%1,%2,%3};"
        : "+f"(c[0]), "+f"(c[1]), "+f"(c[2]), "+f"(c[3])
        : "r"(a[0]), "r"(a[1]), "r"(a[2]), "r"(a[3]), "r"(b[0]), "r"(b[1]));
}

__global__ void __launch_bounds__(256, 2)
gemm_mma_kernel() {
    extern __shared__ __half sm[];
    int tid = threadIdx.x;
    int lane = tid & 31;
    int w = tid >> 5;
    int rb = blockIdx.x * 128;   // output-col tile
    int n0 = blockIdx.y * 128;   // node-row tile

    // ---- load 3 operand tiles into smem (uint4 = 8 fp16 chunks) ----
    {
        const __half* srcs[3] = {
            g_hh + (size_t)n0 * IND, g_hl + (size_t)n0 * IND,
            g_wh + (size_t)rb * IND };
        const int bases[3] = {SA_HI, SA_LO, SB_HI};
        #pragma unroll
        for (int part = 0; part < 3; part++) {
            const __half* src = srcs[part];
            __half* dstb = sm + bases[part];
            #pragma unroll
            for (int it = 0; it < 8; it++) {
                int t = tid + it * 256;
                int r = t >> 4, cb = (t & 15) * 8;
                uint4 v = *(const uint4*)(src + r * IND + cb);
                *(uint4*)(dstb + r * TS + cb) = v;
            }
        }
    }
    __syncthreads();

    int mw = w & 3;        // m-block: rows mw*32..+31
    int nw = w >> 2;       // n-block: cols nw*64..+63
    int lr = lane >> 2;    // lane/4
    int lc2 = 2 * (lane & 3);

    float c[2][8][4];
    #pragma unroll
    for (int mt = 0; mt < 2; mt++)
        #pragma unroll
        for (int nt = 0; nt < 8; nt++)
            #pragma unroll
            for (int q = 0; q < 4; q++) c[mt][nt][q] = 0.f;

    #pragma unroll
    for (int p = 0; p < 2; p++) {
        const __half* As = sm + (p == 0 ? SA_HI : SA_LO);
        const __half* Bs = sm + SB_HI;
        #pragma unroll
        for (int k0 = 0; k0 < 128; k0 += 16) {
            uint32_t a[2][4], b[8][2];
            #pragma unroll
            for (int mt = 0; mt < 2; mt++) {
                const __half* pa = As + (mw * 32 + mt * 16 + lr) * TS + k0 + lc2;
                a[mt][0] = *(const uint32_t*)(pa);
                a[mt][1] = *(const uint32_t*)(pa + 8 * TS);
                a[mt][2] = *(const uint32_t*)(pa + 8);
                a[mt][3] = *(const uint32_t*)(pa + 8 * TS + 8);
            }
            #pragma unroll
            for (int nt = 0; nt < 8; nt++) {
                const __half* pb = Bs + (nw * 64 + nt * 8 + lr) * TS + k0 + lc2;
                b[nt][0] = *(const uint32_t*)(pb);
                b[nt][1] = *(const uint32_t*)(pb + 8);
            }
            #pragma unroll
            for (int mt = 0; mt < 2; mt++)
                #pragma unroll
                for (int nt = 0; nt < 8; nt++)
                    mma16816(c[mt][nt], a[mt], b[nt]);
        }
    }

    // ---- epilogue: registers -> global with bias ----
    bool extras = (rb >= 4096);
    #pragma unroll
    for (int nt = 0; nt < 8; nt++) {
        int colL = nw * 64 + nt * 8 + lc2;
        float b0 = __ldg(&g_bias[rb + colL]);
        float b1 = __ldg(&g_bias[rb + colL + 1]);
        #pragma unroll
        for (int mt = 0; mt < 2; mt++) {
            int row = n0 + mw * 32 + mt * 16 + lr;
            float2 v0 = {c[mt][nt][0] + b0, c[mt][nt][1] + b1};
            float2 v1 = {c[mt][nt][2] + b0, c[mt][nt][3] + b1};
            if (!extras) {
                *(float2*)&g_A[(size_t)row * 4096 + rb + colL]       = v0;
                *(float2*)&g_A[(size_t)(row + 8) * 4096 + rb + colL] = v1;
            } else {
                *(float2*)&g_X[(size_t)row * XW + (rb - 4096) + colL]       = v0;
                *(float2*)&g_X[(size_t)(row + 8) * XW + (rb - 4096) + colL] = v1;
            }
        }
    }
}

// ---------------- edge grouping (counting sort by src) ---------------------
__global__ void zero_kernel() {
    int idx = blockIdx.x * blockDim.x + threadIdx.x;
    if (idx < NN) { g_cnt[idx] = 0; g_cur[idx] = 0; }
}
__global__ void hist_kernel(const int* __restrict__ src) {
    int e = blockIdx.x * blockDim.x + threadIdx.x;
    if (e < EE) atomicAdd(&g_cnt[src[e]], 1);
}
__global__ void scan_kernel() {
    __shared__ int ssum[1024];
    int t = threadIdx.x;
    int vals[8];
    int base = t * 8;
    int s = 0;
    #pragma unroll
    for (int q = 0; q < 8; q++) { vals[q] = g_cnt[base + q]; s += vals[q]; }
    ssum[t] = s;
    __syncthreads();
    for (int off = 1; off < 1024; off <<= 1) {
        int v = (t >= off) ? ssum[t - off] : 0;
        __syncthreads();
        if (t >= off) ssum[t] += v;
        __syncthreads();
    }
    int excl = ssum[t] - s;
    #pragma unroll
    for (int q = 0; q < 8; q++) { g_off[base + q] = excl; excl += vals[q]; }
    if (t == 1023) g_off[NN] = excl;
}
__global__ void scatter_kernel(const int* __restrict__ src) {
    int e = blockIdx.x * blockDim.x + threadIdx.x;
    if (e < EE) {
        int sidx = src[e];
        int pos = g_off[sidx] + atomicAdd(&g_cur[sidx], 1);
        g_perm[pos] = e;
    }
}

// ---------------- edge kernel: one block per src node ----------------------
__global__ void __launch_bounds__(256)
edge_kernel(const int* __restrict__ dst, float* __restrict__ out) {
    __shared__ float sA[64 * 68];
    __shared__ float pd[4 * 68];
    __shared__ float sLs[64];
    __shared__ float sc[64];

    int n = blockIdx.x;
    int start = g_off[n];
    int cnt = g_off[n + 1] - start;
    if (cnt == 0) return;

    int tid = threadIdx.x;
    for (int idx = tid; idx < 4096; idx += 256) {
        int i = idx >> 6, d = idx & 63;
        sA[i * 68 + d] = g_A[(size_t)n * 4096 + idx];
    }
    if (tid < 64) {
        sLs[tid] = g_X[(size_t)n * XW + 64 + tid];
        sc[tid]  = g_c[tid];
    }
    __syncthreads();

    int slot = tid >> 6;
    int i = tid & 63;

    for (int b = 0; b < cnt; b += 4) {
        int ei = b + slot;
        bool valid = (ei < cnt);
        int e = 0;
        float ldv = 0.f;
        if (valid) {
            e = g_perm[start + ei];
            int dn = dst[e];
            pd[slot * 68 + i] = g_X[(size_t)dn * XW + i];
            ldv = g_X[(size_t)dn * XW + 128 + i];
        }
        __syncthreads();
        if (valid) {
            float acc = sLs[i] + ldv + sc[i];
            #pragma unroll
            for (int d4 = 0; d4 < 16; d4++) {
                float4 a = *(const float4*)&sA[i * 68 + d4 * 4];
                float4 p = *(const float4*)&pd[slot * 68 + d4 * 4];
                acc += a.x * p.x + a.y * p.y + a.z * p.z + a.w * p.w;
            }
            out[(size_t)e * 64 + i] = fmaxf(acc, 0.f);
        }
        __syncthreads();
    }
}

// ---------------- launch ---------------------------------------------------
extern "C" void kernel_launch(void* const* d_in, const int* in_sizes, int n_in,
                              void* d_out, int out_size) {
    const float* h       = (const float*)d_in[0];
    const int*   src     = (const int*)  d_in[1];
    const int*   dst     = (const int*)  d_in[2];
    const float* proj1_w = (const float*)d_in[3];
    const float* proj1_b = (const float*)d_in[4];
    const float* proj2_w = (const float*)d_in[5];
    const float* proj2_b = (const float*)d_in[6];
    const float* conv_w  = (const float*)d_in[7];
    const float* conv_b  = (const float*)d_in[8];
    const float* ep2_w   = (const float*)d_in[9];
    const float* ep2_b   = (const float*)d_in[10];
    const float* ep3_w   = (const float*)d_in[11];
    const float* ep3_b   = (const float*)d_in[12];
    const float* bn_g    = (const float*)d_in[13];
    const float* bn_b    = (const float*)d_in[14];
    const float* bn_m    = (const float*)d_in[15];
    const float* bn_v    = (const float*)d_in[16];
    float* out = (float*)d_out;

    cudaFuncSetAttribute(gemm_mma_kernel,
                         cudaFuncAttributeMaxDynamicSharedMemorySize,
                         SM_FP16 * (int)sizeof(__half));

    // launch index 3 = gemm (the slot ncu profiles)
    prep1_kernel<<<64, 128>>>(ep2_w, ep2_b, ep3_w, ep3_b, proj1_b,
                              proj2_w, proj2_b, conv_w, conv_b,
                              bn_g, bn_b, bn_m, bn_v);
    prep2_kernel<<<128, 256>>>(proj1_w, ep3_w, bn_g, bn_v);
    conv_hw_kernel<<<(NN * IND + NEXT * IND) / 4 / 256, 256>>>(h);
    gemm_mma_kernel<<<dim3(NEXT / 128, NN / 128), 256,
                      SM_FP16 * (int)sizeof(__half)>>>();
    zero_kernel<<<(NN + 511) / 512, 512>>>();
    hist_kernel<<<EE / 256, 256>>>(src);
    scan_kernel<<<1, 1024>>>();
    scatter_kernel<<<EE / 256, 256>>>(src);
    edge_kernel<<<NN, 256>>>(dst, out);
}

// round 10
// speedup vs baseline: 1.2274x; 1.2274x over previous
#include <cuda_runtime.h>
#include <cuda_fp16.h>
#include <cstdint>

#define NN      8192
#define EE      65536
#define IND     128
#define HID     64
#define NEXT    4352        // 4096 (A'') + 64 (p2) + 64 (Ls) + 64 (Ld) + 64 (pad)
#define XW      256         // extras row width: p2[0:64] Ls[64:128] Ld[128:192] pad[192:256]
#define BN_EPS  1e-5f

// ---------------- scratch (device globals; allocation-free) ----------------
__device__ float  g_W[NEXT * IND];          // extended weight  [4352,128] fp32
__device__ float  g_bias[NEXT];             // extended bias
__device__ __half g_Ah[(size_t)NN * 4096];  // per-node A'' [8192,4096] fp16 ~67MB
__device__ float  g_X[(size_t)NN * XW];     // per-node extras [8192,256] fp32 8MB
__device__ float  g_c[HID];                 // per-channel constant (bias+BN folded)
__device__ __half g_hh[NN * IND];           // h hi (fp16)
__device__ __half g_hl[NN * IND];           // h lo (fp16)
__device__ __half g_wh[NEXT * IND];         // W hi (fp16)
__device__ int    g_cnt[NN];
__device__ int    g_cur[NN];
__device__ int    g_off[NN + 1];
__device__ int    g_perm[EE];

// ---------------- prep 1: extra weight rows, biases, constants -------------
__global__ void prep1_kernel(const float* __restrict__ ep2w,
                             const float* __restrict__ ep2b,
                             const float* __restrict__ ep3w,
                             const float* __restrict__ ep3b,
                             const float* __restrict__ proj1b,
                             const float* __restrict__ proj2w,
                             const float* __restrict__ proj2b,
                             const float* __restrict__ convw,
                             const float* __restrict__ convb,
                             const float* __restrict__ gamma,
                             const float* __restrict__ beta,
                             const float* __restrict__ mean,
                             const float* __restrict__ var) {
    __shared__ float red[128];
    int i = blockIdx.x;
    int w = threadIdx.x;
    float s = gamma[i] * rsqrtf(var[i] + BN_EPS);

    float e0 = ep2w[i * IND + w];
    float ep = (w + 1 < IND) ? ep2w[i * IND + w + 1] : 0.f;
    float em = (w >= 1)      ? ep2w[i * IND + w - 1] : 0.f;
    g_W[(4160 + i) * IND + w] = s * (convw[0] * ep + convw[1] * e0 + convw[2] * em); // Ls
    g_W[(4224 + i) * IND + w] = s * (convw[3] * ep + convw[4] * e0 + convw[5] * em); // Ld
    g_W[(4096 + i) * IND + w] = proj2w[i * IND + w];                                 // p2
    g_W[(4288 + i) * IND + w] = 0.f;                                                 // pad

    red[w] = e0;
    __syncthreads();
    for (int o = 64; o > 0; o >>= 1) {
        if (w < o) red[w] += red[w + o];
        __syncthreads();
    }
    if (w == 0) {
        float tot = red[0];
        g_c[i] = s * (ep3b[i] + convb[0] * tot + ep2b[i]) + beta[i] - mean[i] * s;
        g_bias[4096 + i] = proj2b[i];
        g_bias[4160 + i] = 0.f;
        g_bias[4224 + i] = 0.f;
        g_bias[4288 + i] = 0.f;
    }
    if (w < 64) {
        int d = w;
        float acc = 0.f;
        #pragma unroll 8
        for (int j = 0; j < 64; j++) acc += ep3w[i * 64 + j] * proj1b[j * 64 + d];
        g_bias[i * 64 + d] = s * acc;
    }
}

// ---------------- prep 2: main W'' rows = s_i * ep3 @ proj1_flat -----------
// also zeroes g_cnt/g_cur (used by the histogram fused into conv_hw)
__global__ void prep2_kernel(const float* __restrict__ proj1w,
                             const float* __restrict__ ep3w,
                             const float* __restrict__ gamma,
                             const float* __restrict__ var) {
    __shared__ float ep3s[4096];
    __shared__ float ptile[4096];
    __shared__ float ss[64];
    int tid = threadIdx.x;
    int gtid = blockIdx.x * 256 + tid;     // 32768 threads total
    if (gtid < NN) { g_cnt[gtid] = 0; g_cur[gtid] = 0; }
    int mb = blockIdx.x * 64;
    for (int idx = tid; idx < 4096; idx += 256) ep3s[idx] = ep3w[idx];
    if (tid < 64) ss[tid] = gamma[tid] * rsqrtf(var[tid] + BN_EPS);
    for (int idx = tid; idx < 4096; idx += 256) {
        int j = idx >> 6, mm = idx & 63;
        ptile[idx] = proj1w[j * 8192 + mb + mm];
    }
    __syncthreads();
    for (int o = tid; o < 4096; o += 256) {
        int i = o >> 6, mm = o & 63;
        float acc = 0.f;
        #pragma unroll 8
        for (int j = 0; j < 64; j++) acc += ep3s[i * 64 + j] * ptile[j * 64 + mm];
        int m = mb + mm;
        int d = m >> 7, w = m & 127;
        g_W[(i * 64 + d) * IND + w] = ss[i] * acc;
    }
}

// ---------------- fused fp16 hi/lo converter (h and W) + src histogram -----
// grid covers h (1,048,576 el) then W (557,056 el), 4 el/thread; 401,408 threads
__global__ void conv_hw_kernel(const float* __restrict__ h,
                               const int* __restrict__ src) {
    int tid = blockIdx.x * 256 + threadIdx.x;
    int idx = tid * 4;
    if (idx < NN * IND) {
        float4 v = *(const float4*)&h[idx];
        float xs[4] = {v.x, v.y, v.z, v.w};
        #pragma unroll
        for (int q = 0; q < 4; q++) {
            __half hi = __float2half_rn(xs[q]);
            g_hh[idx + q] = hi;
            g_hl[idx + q] = __float2half_rn(xs[q] - __half2float(hi));
        }
    } else {
        int j = idx - NN * IND;
        float4 v = *(const float4*)&g_W[j];
        float xs[4] = {v.x, v.y, v.z, v.w};
        #pragma unroll
        for (int q = 0; q < 4; q++)
            g_wh[j + q] = __float2half_rn(xs[q]);
    }
    if (tid < EE) atomicAdd(&g_cnt[src[tid]], 1);
}

// ---------------- HMMA GEMM: [g_Ah|g_X] = h @ W^T + bias -------------------
// mma.sync.m16n8k16 fp16, 2-pass hi/lo split (hi_h*hi_w + lo_h*hi_w), fp32 acc.
// CTA = 128x128 tile, K=128 resident, 3 smem tiles -> 2 CTAs/SM.
// 8 warps = 4(m) x 2(n); per warp 32x64 = 2 m16-tiles x 8 n8-tiles.
// Main A'' block stored fp16; extras block stored fp32 to g_X.
#define TS       136                 // smem row stride in fp16 (272B; conflict-free frags)
#define SA_HI    0
#define SA_LO    (128 * TS)
#define SB_HI    (2 * 128 * TS)
#define SM_FP16  (3 * 128 * TS)      // 52224 halfs = 104448 bytes

__device__ __forceinline__ void mma16816(float* c, const uint32_t* a, const uint32_t* b) {
    asm volatile(
        "mma.sync.aligned.m16n8k16.row.col.f32.f16.f16.f32 "
        "{%0,%1,%2,%3}, {%4,%5,%6,%7}, {%8,%9}, {%0,%1,%2,%3};"
        : "+f"(c[0]), "+f"(c[1]), "+f"(c[2]), "+f"(c[3])
        : "r"(a[0]), "r"(a[1]), "r"(a[2]), "r"(a[3]), "r"(b[0]), "r"(b[1]));
}

__global__ void __launch_bounds__(256, 2)
gemm_mma_kernel() {
    extern __shared__ __half sm[];
    int tid = threadIdx.x;
    int lane = tid & 31;
    int w = tid >> 5;
    int rb = blockIdx.x * 128;   // output-col tile
    int n0 = blockIdx.y * 128;   // node-row tile

    // ---- load 3 operand tiles into smem (uint4 = 8 fp16 chunks) ----
    {
        const __half* srcs[3] = {
            g_hh + (size_t)n0 * IND, g_hl + (size_t)n0 * IND,
            g_wh + (size_t)rb * IND };
        const int bases[3] = {SA_HI, SA_LO, SB_HI};
        #pragma unroll
        for (int part = 0; part < 3; part++) {
            const __half* src = srcs[part];
            __half* dstb = sm + bases[part];
            #pragma unroll
            for (int it = 0; it < 8; it++) {
                int t = tid + it * 256;
                int r = t >> 4, cb = (t & 15) * 8;
                uint4 v = *(const uint4*)(src + r * IND + cb);
                *(uint4*)(dstb + r * TS + cb) = v;
            }
        }
    }
    __syncthreads();

    int mw = w & 3;        // m-block: rows mw*32..+31
    int nw = w >> 2;       // n-block: cols nw*64..+63
    int lr = lane >> 2;    // lane/4
    int lc2 = 2 * (lane & 3);

    float c[2][8][4];
    #pragma unroll
    for (int mt = 0; mt < 2; mt++)
        #pragma unroll
        for (int nt = 0; nt < 8; nt++)
            #pragma unroll
            for (int q = 0; q < 4; q++) c[mt][nt][q] = 0.f;

    #pragma unroll
    for (int p = 0; p < 2; p++) {
        const __half* As = sm + (p == 0 ? SA_HI : SA_LO);
        const __half* Bs = sm + SB_HI;
        #pragma unroll
        for (int k0 = 0; k0 < 128; k0 += 16) {
            uint32_t a[2][4], b[8][2];
            #pragma unroll
            for (int mt = 0; mt < 2; mt++) {
                const __half* pa = As + (mw * 32 + mt * 16 + lr) * TS + k0 + lc2;
                a[mt][0] = *(const uint32_t*)(pa);
                a[mt][1] = *(const uint32_t*)(pa + 8 * TS);
                a[mt][2] = *(const uint32_t*)(pa + 8);
                a[mt][3] = *(const uint32_t*)(pa + 8 * TS + 8);
            }
            #pragma unroll
            for (int nt = 0; nt < 8; nt++) {
                const __half* pb = Bs + (nw * 64 + nt * 8 + lr) * TS + k0 + lc2;
                b[nt][0] = *(const uint32_t*)(pb);
                b[nt][1] = *(const uint32_t*)(pb + 8);
            }
            #pragma unroll
            for (int mt = 0; mt < 2; mt++)
                #pragma unroll
                for (int nt = 0; nt < 8; nt++)
                    mma16816(c[mt][nt], a[mt], b[nt]);
        }
    }

    // ---- epilogue: registers -> global with bias ----
    bool extras = (rb >= 4096);
    #pragma unroll
    for (int nt = 0; nt < 8; nt++) {
        int colL = nw * 64 + nt * 8 + lc2;
        float b0 = __ldg(&g_bias[rb + colL]);
        float b1 = __ldg(&g_bias[rb + colL + 1]);
        #pragma unroll
        for (int mt = 0; mt < 2; mt++) {
            int row = n0 + mw * 32 + mt * 16 + lr;
            if (!extras) {
                __half2 v0 = __floats2half2_rn(c[mt][nt][0] + b0, c[mt][nt][1] + b1);
                __half2 v1 = __floats2half2_rn(c[mt][nt][2] + b0, c[mt][nt][3] + b1);
                *(__half2*)&g_Ah[(size_t)row * 4096 + rb + colL]       = v0;
                *(__half2*)&g_Ah[(size_t)(row + 8) * 4096 + rb + colL] = v1;
            } else {
                float2 v0 = {c[mt][nt][0] + b0, c[mt][nt][1] + b1};
                float2 v1 = {c[mt][nt][2] + b0, c[mt][nt][3] + b1};
                *(float2*)&g_X[(size_t)row * XW + (rb - 4096) + colL]       = v0;
                *(float2*)&g_X[(size_t)(row + 8) * XW + (rb - 4096) + colL] = v1;
            }
        }
    }
}

// ---------------- scan + scatter (counting sort by src) --------------------
__global__ void scan_kernel() {
    __shared__ int ssum[1024];
    int t = threadIdx.x;
    int vals[8];
    int base = t * 8;
    int s = 0;
    #pragma unroll
    for (int q = 0; q < 8; q++) { vals[q] = g_cnt[base + q]; s += vals[q]; }
    ssum[t] = s;
    __syncthreads();
    for (int off = 1; off < 1024; off <<= 1) {
        int v = (t >= off) ? ssum[t - off] : 0;
        __syncthreads();
        if (t >= off) ssum[t] += v;
        __syncthreads();
    }
    int excl = ssum[t] - s;
    #pragma unroll
    for (int q = 0; q < 8; q++) { g_off[base + q] = excl; excl += vals[q]; }
    if (t == 1023) g_off[NN] = excl;
}
__global__ void scatter_kernel(const int* __restrict__ src) {
    int e = blockIdx.x * blockDim.x + threadIdx.x;
    if (e < EE) {
        int sidx = src[e];
        int pos = g_off[sidx] + atomicAdd(&g_cur[sidx], 1);
        g_perm[pos] = e;
    }
}

// ---------------- edge kernel: one block (512 thr) per src node ------------
// out[e,i] = relu( A''[src,i,:] . p2[dst] + Ls'[src,i] + Ld'[dst,i] + c[i] )
__global__ void __launch_bounds__(512)
edge_kernel(const int* __restrict__ dst, float* __restrict__ out) {
    __shared__ float sA[64 * 68];   // A''[n] fp32, padded rows
    __shared__ float pd[8 * 68];    // p2[dst] per edge slot
    __shared__ float sLs[64];
    __shared__ float sc[64];

    int n = blockIdx.x;
    int start = g_off[n];
    int cnt = g_off[n + 1] - start;
    if (cnt == 0) return;

    int tid = threadIdx.x;
    // vectorized fp16 load of A'' row: 512 threads x 1 uint4 (8 halfs)
    {
        uint4 v = *(const uint4*)&g_Ah[(size_t)n * 4096 + tid * 8];
        const __half* hp = (const __half*)&v;
        int i = tid >> 3, dbase = (tid & 7) * 8;
        #pragma unroll
        for (int q = 0; q < 8; q++)
            sA[i * 68 + dbase + q] = __half2float(hp[q]);
    }
    if (tid < 64) {
        sLs[tid] = g_X[(size_t)n * XW + 64 + tid];
        sc[tid]  = g_c[tid];
    }
    __syncthreads();

    int slot = tid >> 6;   // 0..7
    int i = tid & 63;

    for (int b = 0; b < cnt; b += 8) {
        int ei = b + slot;
        bool valid = (ei < cnt);
        int e = 0;
        float ldv = 0.f;
        if (valid) {
            e = g_perm[start + ei];
            int dn = dst[e];
            pd[slot * 68 + i] = g_X[(size_t)dn * XW + i];
            ldv = g_X[(size_t)dn * XW + 128 + i];
        }
        __syncthreads();
        if (valid) {
            float acc = sLs[i] + ldv + sc[i];
            #pragma unroll
            for (int d4 = 0; d4 < 16; d4++) {
                float4 a = *(const float4*)&sA[i * 68 + d4 * 4];
                float4 p = *(const float4*)&pd[slot * 68 + d4 * 4];
                acc += a.x * p.x + a.y * p.y + a.z * p.z + a.w * p.w;
            }
            out[(size_t)e * 64 + i] = fmaxf(acc, 0.f);
        }
        __syncthreads();
    }
}

// ---------------- launch ---------------------------------------------------
extern "C" void kernel_launch(void* const* d_in, const int* in_sizes, int n_in,
                              void* d_out, int out_size) {
    const float* h       = (const float*)d_in[0];
    const int*   src     = (const int*)  d_in[1];
    const int*   dst     = (const int*)  d_in[2];
    const float* proj1_w = (const float*)d_in[3];
    const float* proj1_b = (const float*)d_in[4];
    const float* proj2_w = (const float*)d_in[5];
    const float* proj2_b = (const float*)d_in[6];
    const float* conv_w  = (const float*)d_in[7];
    const float* conv_b  = (const float*)d_in[8];
    const float* ep2_w   = (const float*)d_in[9];
    const float* ep2_b   = (const float*)d_in[10];
    const float* ep3_w   = (const float*)d_in[11];
    const float* ep3_b   = (const float*)d_in[12];
    const float* bn_g    = (const float*)d_in[13];
    const float* bn_b    = (const float*)d_in[14];
    const float* bn_m    = (const float*)d_in[15];
    const float* bn_v    = (const float*)d_in[16];
    float* out = (float*)d_out;

    cudaFuncSetAttribute(gemm_mma_kernel,
                         cudaFuncAttributeMaxDynamicSharedMemorySize,
                         SM_FP16 * (int)sizeof(__half));

    // launch index 3 = gemm (the slot ncu profiles)
    prep1_kernel<<<64, 128>>>(ep2_w, ep2_b, ep3_w, ep3_b, proj1_b,
                              proj2_w, proj2_b, conv_w, conv_b,
                              bn_g, bn_b, bn_m, bn_v);
    prep2_kernel<<<128, 256>>>(proj1_w, ep3_w, bn_g, bn_v);
    conv_hw_kernel<<<(NN * IND + NEXT * IND) / 4 / 256, 256>>>(h, src);
    gemm_mma_kernel<<<dim3(NEXT / 128, NN / 128), 256,
                      SM_FP16 * (int)sizeof(__half)>>>();
    scan_kernel<<<1, 1024>>>();
    scatter_kernel<<<EE / 256, 256>>>(src);
    edge_kernel<<<NN, 512>>>(dst, out);
}

// round 13
// speedup vs baseline: 1.3910x; 1.1332x over previous
#include <cuda_runtime.h>
#include <cuda_fp16.h>
#include <cstdint>

#define NN      8192
#define EE      65536
#define IND     128
#define HID     64
#define NEXT    4352        // 4096 (A'') + 64 (p2) + 64 (Ls) + 64 (Ld) + 64 (pad)
#define XW      256         // extras row width: p2[0:64] Ls[64:128] Ld[128:192] pad[192:256]
#define BN_EPS  1e-5f

// ---------------- scratch (device globals; allocation-free) ----------------
__device__ float  g_W[NEXT * IND];          // extended weight  [4352,128] fp32
__device__ float  g_bias[NEXT];             // extended bias
__device__ __half g_Ah[(size_t)NN * 4096];  // per-node A'' [8192,4096] fp16 ~67MB
__device__ float  g_X[(size_t)NN * XW];     // per-node extras [8192,256] fp32 8MB
__device__ float  g_c[HID];                 // per-channel constant (bias+BN folded)
__device__ __half g_hh[NN * IND];           // h hi (fp16)
__device__ __half g_hl[NN * IND];           // h lo (fp16)
__device__ __half g_wh[NEXT * IND];         // W hi (fp16)
__device__ int    g_cnt[NN];
__device__ int    g_cur[NN];
__device__ int    g_off[NN + 1];
__device__ int    g_perm[EE];

// ---------------- prep 1: extra weight rows, biases, constants -------------
__global__ void prep1_kernel(const float* __restrict__ ep2w,
                             const float* __restrict__ ep2b,
                             const float* __restrict__ ep3w,
                             const float* __restrict__ ep3b,
                             const float* __restrict__ proj1b,
                             const float* __restrict__ proj2w,
                             const float* __restrict__ proj2b,
                             const float* __restrict__ convw,
                             const float* __restrict__ convb,
                             const float* __restrict__ gamma,
                             const float* __restrict__ beta,
                             const float* __restrict__ mean,
                             const float* __restrict__ var) {
    __shared__ float red[128];
    int i = blockIdx.x;
    int w = threadIdx.x;
    float s = gamma[i] * rsqrtf(var[i] + BN_EPS);

    float e0 = ep2w[i * IND + w];
    float ep = (w + 1 < IND) ? ep2w[i * IND + w + 1] : 0.f;
    float em = (w >= 1)      ? ep2w[i * IND + w - 1] : 0.f;
    g_W[(4160 + i) * IND + w] = s * (convw[0] * ep + convw[1] * e0 + convw[2] * em); // Ls
    g_W[(4224 + i) * IND + w] = s * (convw[3] * ep + convw[4] * e0 + convw[5] * em); // Ld
    g_W[(4096 + i) * IND + w] = proj2w[i * IND + w];                                 // p2
    g_W[(4288 + i) * IND + w] = 0.f;                                                 // pad

    red[w] = e0;
    __syncthreads();
    for (int o = 64; o > 0; o >>= 1) {
        if (w < o) red[w] += red[w + o];
        __syncthreads();
    }
    if (w == 0) {
        float tot = red[0];
        g_c[i] = s * (ep3b[i] + convb[0] * tot + ep2b[i]) + beta[i] - mean[i] * s;
        g_bias[4096 + i] = proj2b[i];
        g_bias[4160 + i] = 0.f;
        g_bias[4224 + i] = 0.f;
        g_bias[4288 + i] = 0.f;
    }
    if (w < 64) {
        int d = w;
        float acc = 0.f;
        #pragma unroll 8
        for (int j = 0; j < 64; j++) acc += ep3w[i * 64 + j] * proj1b[j * 64 + d];
        g_bias[i * 64 + d] = s * acc;
    }
}

// ---------------- prep 2: main W'' rows = s_i * ep3 @ proj1_flat -----------
// also zeroes g_cnt/g_cur (used by the histogram fused into conv_hw)
__global__ void prep2_kernel(const float* __restrict__ proj1w,
                             const float* __restrict__ ep3w,
                             const float* __restrict__ gamma,
                             const float* __restrict__ var) {
    __shared__ float ep3s[4096];
    __shared__ float ptile[4096];
    __shared__ float ss[64];
    int tid = threadIdx.x;
    int gtid = blockIdx.x * 256 + tid;     // 32768 threads total
    if (gtid < NN) { g_cnt[gtid] = 0; g_cur[gtid] = 0; }
    int mb = blockIdx.x * 64;
    for (int idx = tid; idx < 4096; idx += 256) ep3s[idx] = ep3w[idx];
    if (tid < 64) ss[tid] = gamma[tid] * rsqrtf(var[tid] + BN_EPS);
    for (int idx = tid; idx < 4096; idx += 256) {
        int j = idx >> 6, mm = idx & 63;
        ptile[idx] = proj1w[j * 8192 + mb + mm];
    }
    __syncthreads();
    for (int o = tid; o < 4096; o += 256) {
        int i = o >> 6, mm = o & 63;
        float acc = 0.f;
        #pragma unroll 8
        for (int j = 0; j < 64; j++) acc += ep3s[i * 64 + j] * ptile[j * 64 + mm];
        int m = mb + mm;
        int d = m >> 7, w = m & 127;
        g_W[(i * 64 + d) * IND + w] = ss[i] * acc;
    }
}

// ---------------- fused fp16 hi/lo converter (h and W) + src histogram -----
// grid covers h (1,048,576 el) then W (557,056 el), 4 el/thread; 401,408 threads
__global__ void conv_hw_kernel(const float* __restrict__ h,
                               const int* __restrict__ src) {
    int tid = blockIdx.x * 256 + threadIdx.x;
    int idx = tid * 4;
    if (idx < NN * IND) {
        float4 v = *(const float4*)&h[idx];
        float xs[4] = {v.x, v.y, v.z, v.w};
        #pragma unroll
        for (int q = 0; q < 4; q++) {
            __half hi = __float2half_rn(xs[q]);
            g_hh[idx + q] = hi;
            g_hl[idx + q] = __float2half_rn(xs[q] - __half2float(hi));
        }
    } else {
        int j = idx - NN * IND;
        float4 v = *(const float4*)&g_W[j];
        float xs[4] = {v.x, v.y, v.z, v.w};
        #pragma unroll
        for (int q = 0; q < 4; q++)
            g_wh[j + q] = __float2half_rn(xs[q]);
    }
    if (tid < EE) atomicAdd(&g_cnt[src[tid]], 1);
}

// ---------------- HMMA GEMM: [g_Ah|g_X] = h @ W^T + bias -------------------
// mma.sync.m16n8k16 fp16, 2-pass hi/lo split (hi_h*hi_w + lo_h*hi_w), fp32 acc.
// CTA = 64x128 tile, K=128 resident, 3 smem tiles (~68KB) -> 3 CTAs/SM.
// 8 warps = 2(m) x 4(n); per warp 32x32 = 2 m16-tiles x 4 n8-tiles.
#define TS       136                 // smem row stride in fp16 (272B; conflict-free frags)
#define SA_HI    0
#define SA_LO    (64 * TS)
#define SB_HI    (2 * 64 * TS)
#define SM_FP16  (2 * 64 * TS + 128 * TS)    // 34816 halfs = 69632 bytes

__device__ __forceinline__ void mma16816(float* c, const uint32_t* a, const uint32_t* b) {
    asm volatile(
        "mma.sync.aligned.m16n8k16.row.col.f32.f16.f16.f32 "
        "{%0,%1,%2,%3}, {%4,%5,%6,%7}, {%8,%9}, {%0,%1,%2,%3};"
        : "+f"(c[0]), "+f"(c[1]), "+f"(c[2]), "+f"(c[3])
        : "r"(a[0]), "r"(a[1]), "r"(a[2]), "r"(a[3]), "r"(b[0]), "r"(b[1]));
}

__global__ void __launch_bounds__(256, 3)
gemm_mma_kernel() {
    extern __shared__ __half sm[];
    int tid = threadIdx.x;
    int lane = tid & 31;
    int w = tid >> 5;
    int rb = blockIdx.x * 128;   // output-col tile
    int n0 = blockIdx.y * 64;    // node-row tile

    // ---- fill smem: A hi/lo (64x128) + B hi (128x128), uint4 chunks ----
    {
        const __half* srcA[2] = { g_hh + (size_t)n0 * IND, g_hl + (size_t)n0 * IND };
        #pragma unroll
        for (int part = 0; part < 2; part++) {
            __half* dstb = sm + (part == 0 ? SA_HI : SA_LO);
            #pragma unroll
            for (int it = 0; it < 4; it++) {
                int t = tid + it * 256;          // 1024 chunks
                int r = t >> 4, cb = (t & 15) * 8;
                uint4 v = *(const uint4*)(srcA[part] + r * IND + cb);
                *(uint4*)(dstb + r * TS + cb) = v;
            }
        }
        const __half* srcB = g_wh + (size_t)rb * IND;
        __half* dstb = sm + SB_HI;
        #pragma unroll
        for (int it = 0; it < 8; it++) {
            int t = tid + it * 256;              // 2048 chunks
            int r = t >> 4, cb = (t & 15) * 8;
            uint4 v = *(const uint4*)(srcB + r * IND + cb);
            *(uint4*)(dstb + r * TS + cb) = v;
        }
    }
    __syncthreads();

    int mw = w & 1;        // m-block: rows mw*32..+31
    int nw = w >> 1;       // n-block: cols nw*32..+31
    int lr = lane >> 2;    // lane/4
    int lc2 = 2 * (lane & 3);

    float c[2][4][4];
    #pragma unroll
    for (int mt = 0; mt < 2; mt++)
        #pragma unroll
        for (int nt = 0; nt < 4; nt++)
            #pragma unroll
            for (int q = 0; q < 4; q++) c[mt][nt][q] = 0.f;

    #pragma unroll
    for (int p = 0; p < 2; p++) {
        const __half* As = sm + (p == 0 ? SA_HI : SA_LO);
        const __half* Bs = sm + SB_HI;
        #pragma unroll
        for (int k0 = 0; k0 < 128; k0 += 16) {
            uint32_t a[2][4], b[4][2];
            #pragma unroll
            for (int mt = 0; mt < 2; mt++) {
                const __half* pa = As + (mw * 32 + mt * 16 + lr) * TS + k0 + lc2;
                a[mt][0] = *(const uint32_t*)(pa);
                a[mt][1] = *(const uint32_t*)(pa + 8 * TS);
                a[mt][2] = *(const uint32_t*)(pa + 8);
                a[mt][3] = *(const uint32_t*)(pa + 8 * TS + 8);
            }
            #pragma unroll
            for (int nt = 0; nt < 4; nt++) {
                const __half* pb = Bs + (nw * 32 + nt * 8 + lr) * TS + k0 + lc2;
                b[nt][0] = *(const uint32_t*)(pb);
                b[nt][1] = *(const uint32_t*)(pb + 8);
            }
            #pragma unroll
            for (int mt = 0; mt < 2; mt++)
                #pragma unroll
                for (int nt = 0; nt < 4; nt++)
                    mma16816(c[mt][nt], a[mt], b[nt]);
        }
    }

    // ---- epilogue: registers -> global with bias ----
    bool extras = (rb >= 4096);
    #pragma unroll
    for (int nt = 0; nt < 4; nt++) {
        int colL = nw * 32 + nt * 8 + lc2;
        float b0 = __ldg(&g_bias[rb + colL]);
        float b1 = __ldg(&g_bias[rb + colL + 1]);
        #pragma unroll
        for (int mt = 0; mt < 2; mt++) {
            int row = n0 + mw * 32 + mt * 16 + lr;
            if (!extras) {
                __half2 v0 = __floats2half2_rn(c[mt][nt][0] + b0, c[mt][nt][1] + b1);
                __half2 v1 = __floats2half2_rn(c[mt][nt][2] + b0, c[mt][nt][3] + b1);
                *(__half2*)&g_Ah[(size_t)row * 4096 + rb + colL]       = v0;
                *(__half2*)&g_Ah[(size_t)(row + 8) * 4096 + rb + colL] = v1;
            } else {
                float2 v0 = {c[mt][nt][0] + b0, c[mt][nt][1] + b1};
                float2 v1 = {c[mt][nt][2] + b0, c[mt][nt][3] + b1};
                *(float2*)&g_X[(size_t)row * XW + (rb - 4096) + colL]       = v0;
                *(float2*)&g_X[(size_t)(row + 8) * XW + (rb - 4096) + colL] = v1;
            }
        }
    }
}

// ---------------- scan + scatter (counting sort by src) --------------------
__global__ void scan_kernel() {
    __shared__ int ssum[1024];
    int t = threadIdx.x;
    int vals[8];
    int base = t * 8;
    int s = 0;
    #pragma unroll
    for (int q = 0; q < 8; q++) { vals[q] = g_cnt[base + q]; s += vals[q]; }
    ssum[t] = s;
    __syncthreads();
    for (int off = 1; off < 1024; off <<= 1) {
        int v = (t >= off) ? ssum[t - off] : 0;
        __syncthreads();
        if (t >= off) ssum[t] += v;
        __syncthreads();
    }
    int excl = ssum[t] - s;
    #pragma unroll
    for (int q = 0; q < 8; q++) { g_off[base + q] = excl; excl += vals[q]; }
    if (t == 1023) g_off[NN] = excl;
}
__global__ void scatter_kernel(const int* __restrict__ src) {
    int e = blockIdx.x * blockDim.x + threadIdx.x;
    if (e < EE) {
        int sidx = src[e];
        int pos = g_off[sidx] + atomicAdd(&g_cur[sidx], 1);
        g_perm[pos] = e;
    }
}

// ---------------- edge kernel: one block (512 thr) per src node ------------
// out[e,i] = relu( A''[src,i,:] . p2[dst] + Ls'[src,i] + Ld'[dst,i] + c[i] )
// A'' kept in fp16 in smem; convert inside the FMA loop.
#define AST 72   // sAh row stride in halfs (144B; conflict-free for lane-consecutive i)
__global__ void __launch_bounds__(512)
edge_kernel(const int* __restrict__ dst, float* __restrict__ out) {
    __shared__ __half sAh[64 * AST];  // A''[n] fp16
    __shared__ float pd[8 * 68];      // p2[dst] per edge slot
    __shared__ float sLs[64];
    __shared__ float sc[64];

    int n = blockIdx.x;
    int start = g_off[n];
    int cnt = g_off[n + 1] - start;
    if (cnt == 0) return;

    int tid = threadIdx.x;
    // vectorized fp16 load of A'' row: 512 threads x 1 uint4 (8 halfs)
    {
        uint4 v = *(const uint4*)&g_Ah[(size_t)n * 4096 + tid * 8];
        int i = tid >> 3, dbase = (tid & 7) * 8;
        *(uint4*)&sAh[i * AST + dbase] = v;
    }
    if (tid < 64) {
        sLs[tid] = g_X[(size_t)n * XW + 64 + tid];
        sc[tid]  = g_c[tid];
    }
    __syncthreads();

    int slot = tid >> 6;   // 0..7
    int i = tid & 63;

    for (int b = 0; b < cnt; b += 8) {
        int ei = b + slot;
        bool valid = (ei < cnt);
        int e = 0;
        float ldv = 0.f;
        if (valid) {
            e = g_perm[start + ei];
            int dn = dst[e];
            pd[slot * 68 + i] = g_X[(size_t)dn * XW + i];
            ldv = g_X[(size_t)dn * XW + 128 + i];
        }
        __syncthreads();
        if (valid) {
            float acc = sLs[i] + ldv + sc[i];
            #pragma unroll
            for (int d8 = 0; d8 < 8; d8++) {
                uint4 av = *(const uint4*)&sAh[i * AST + d8 * 8];
                const __half2* ah = (const __half2*)&av;
                float4 p0 = *(const float4*)&pd[slot * 68 + d8 * 8];
                float4 p1 = *(const float4*)&pd[slot * 68 + d8 * 8 + 4];
                float2 f0 = __half22float2(ah[0]);
                float2 f1 = __half22float2(ah[1]);
                float2 f2 = __half22float2(ah[2]);
                float2 f3 = __half22float2(ah[3]);
                acc += f0.x * p0.x + f0.y * p0.y + f1.x * p0.z + f1.y * p0.w
                     + f2.x * p1.x + f2.y * p1.y + f3.x * p1.z + f3.y * p1.w;
            }
            out[(size_t)e * 64 + i] = fmaxf(acc, 0.f);
        }
        __syncthreads();
    }
}

// ---------------- launch ---------------------------------------------------
extern "C" void kernel_launch(void* const* d_in, const int* in_sizes, int n_in,
                              void* d_out, int out_size) {
    const float* h       = (const float*)d_in[0];
    const int*   src     = (const int*)  d_in[1];
    const int*   dst     = (const int*)  d_in[2];
    const float* proj1_w = (const float*)d_in[3];
    const float* proj1_b = (const float*)d_in[4];
    const float* proj2_w = (const float*)d_in[5];
    const float* proj2_b = (const float*)d_in[6];
    const float* conv_w  = (const float*)d_in[7];
    const float* conv_b  = (const float*)d_in[8];
    const float* ep2_w   = (const float*)d_in[9];
    const float* ep2_b   = (const float*)d_in[10];
    const float* ep3_w   = (const float*)d_in[11];
    const float* ep3_b   = (const float*)d_in[12];
    const float* bn_g    = (const float*)d_in[13];
    const float* bn_b    = (const float*)d_in[14];
    const float* bn_m    = (const float*)d_in[15];
    const float* bn_v    = (const float*)d_in[16];
    float* out = (float*)d_out;

    cudaFuncSetAttribute(gemm_mma_kernel,
                         cudaFuncAttributeMaxDynamicSharedMemorySize,
                         SM_FP16 * (int)sizeof(__half));

    // launch index 3 = gemm (the slot ncu profiles)
    prep1_kernel<<<64, 128>>>(ep2_w, ep2_b, ep3_w, ep3_b, proj1_b,
                              proj2_w, proj2_b, conv_w, conv_b,
                              bn_g, bn_b, bn_m, bn_v);
    prep2_kernel<<<128, 256>>>(proj1_w, ep3_w, bn_g, bn_v);
    conv_hw_kernel<<<(NN * IND + NEXT * IND) / 4 / 256, 256>>>(h, src);
    gemm_mma_kernel<<<dim3(NEXT / 128, NN / 64), 256,
                      SM_FP16 * (int)sizeof(__half)>>>();
    scan_kernel<<<1, 1024>>>();
    scatter_kernel<<<EE / 256, 256>>>(src);
    edge_kernel<<<NN, 512>>>(dst, out);
}